// round 2
// baseline (speedup 1.0000x reference)
#include <cuda_runtime.h>
#include <cstddef>

// ---------------------------------------------------------------------------
// LuongAttention: context, alignment = attn(query, values, W, b)
//   keys    = values @ W + b                [B, TV, U]
//   score   = query @ keys^T                [B, TQ, TV]   (into alignment buf)
//   align   = softmax(score, axis=-1)       in-place
//   context = align @ values                [B, TQ, D]
// Output buffer: context (B*TQ*D floats) followed by alignment (B*TQ*TV).
// ---------------------------------------------------------------------------

#define B_DIM 16
#define TQ 2048
#define TV 2048
#define D_DIM 1024
#define UNITS 1024

#define TM 128
#define TN 128
#define TK 16

// scratch for keys: 16*2048*1024 floats = 128 MiB (static device array, no alloc)
__device__ float g_keys[(size_t)B_DIM * TV * UNITS];

__device__ __forceinline__ unsigned long long pack2(float lo, float hi) {
    unsigned long long r;
    asm("mov.b64 %0, {%1, %2};" : "=l"(r) : "f"(lo), "f"(hi));
    return r;
}
__device__ __forceinline__ void unpack2(unsigned long long v, float& lo, float& hi) {
    asm("mov.b64 {%0, %1}, %2;" : "=f"(lo), "=f"(hi) : "l"(v));
}
__device__ __forceinline__ unsigned long long fma2(unsigned long long a,
                                                   unsigned long long b,
                                                   unsigned long long c) {
    unsigned long long d;
    asm("fma.rn.f32x2 %0, %1, %2, %3;" : "=l"(d) : "l"(a), "l"(b), "l"(c));
    return d;
}

// Generic fp32 GEMM, C[M,N] = A[M,K] @ op(B) (+bias), op = B^T if BT (B is [N,K])
// else B is [K,N]. Batched via blockIdx.z with element strides sA/sB/sC.
// All of M,N divisible by 128 and K divisible by 16 (true for every call here).
template <bool BT, bool BIAS>
__global__ void __launch_bounds__(256, 2)
gemm_f32x2_kernel(const float* __restrict__ Ab, const float* __restrict__ Bb,
                  const float* __restrict__ bias, float* __restrict__ Cb,
                  int M, int N, int K,
                  size_t sA, size_t sB, size_t sC) {
    __shared__ float As[TK][TM];
    __shared__ float Bs[TK][TN];

    const float* A = Ab + (size_t)blockIdx.z * sA;
    const float* Bp = Bb + (size_t)blockIdx.z * sB;
    float* C = Cb + (size_t)blockIdx.z * sC;

    const int tid = threadIdx.x;
    const int tx = tid & 15;   // column group: cols tx + 16*j
    const int ty = tid >> 4;   // row group:    rows ty*8 + i
    const int bm = blockIdx.y;
    const int bn = blockIdx.x;

    unsigned long long acc[8][4];
#pragma unroll
    for (int i = 0; i < 8; ++i)
#pragma unroll
        for (int p = 0; p < 4; ++p) acc[i][p] = 0ULL;

    const int nk = K / TK;

    float4 a_pre[2], b_pre[2];

    // ---- initial prefetch (k-tile 0) ----
#pragma unroll
    for (int it = 0; it < 2; ++it) {
        const int idx = tid + it * 256;
        const int r = idx >> 2;
        const int cc = (idx & 3) * 4;
        a_pre[it] = *(const float4*)(A + (size_t)(bm * TM + r) * K + cc);
        if (BT) {
            b_pre[it] = *(const float4*)(Bp + (size_t)(bn * TN + r) * K + cc);
        } else {
            const int kk = idx >> 5;
            const int nc = (idx & 31) * 4;
            b_pre[it] = *(const float4*)(Bp + (size_t)kk * N + bn * TN + nc);
        }
    }

    for (int kt = 0; kt < nk; ++kt) {
        // ---- commit prefetched tile to smem ----
#pragma unroll
        for (int it = 0; it < 2; ++it) {
            const int idx = tid + it * 256;
            const int r = idx >> 2;
            const int cc = (idx & 3) * 4;
            As[cc + 0][r] = a_pre[it].x;
            As[cc + 1][r] = a_pre[it].y;
            As[cc + 2][r] = a_pre[it].z;
            As[cc + 3][r] = a_pre[it].w;
            if (BT) {
                Bs[cc + 0][r] = b_pre[it].x;
                Bs[cc + 1][r] = b_pre[it].y;
                Bs[cc + 2][r] = b_pre[it].z;
                Bs[cc + 3][r] = b_pre[it].w;
            } else {
                const int kk = idx >> 5;
                const int nc = (idx & 31) * 4;
                *(float4*)&Bs[kk][nc] = b_pre[it];
            }
        }
        __syncthreads();

        // ---- issue next tile's global loads (latency hidden by compute) ----
        if (kt + 1 < nk) {
            const int k0 = (kt + 1) * TK;
#pragma unroll
            for (int it = 0; it < 2; ++it) {
                const int idx = tid + it * 256;
                const int r = idx >> 2;
                const int cc = (idx & 3) * 4;
                a_pre[it] = *(const float4*)(A + (size_t)(bm * TM + r) * K + k0 + cc);
                if (BT) {
                    b_pre[it] = *(const float4*)(Bp + (size_t)(bn * TN + r) * K + k0 + cc);
                } else {
                    const int kk = idx >> 5;
                    const int nc = (idx & 31) * 4;
                    b_pre[it] = *(const float4*)(Bp + (size_t)(k0 + kk) * N + bn * TN + nc);
                }
            }
        }

        // ---- compute on current tile ----
#pragma unroll
        for (int k = 0; k < TK; ++k) {
            const float4 a0 = *(const float4*)&As[k][ty * 8];
            const float4 a1 = *(const float4*)&As[k][ty * 8 + 4];
            float bj[8];
#pragma unroll
            for (int j = 0; j < 8; ++j) bj[j] = Bs[k][tx + 16 * j];
            const unsigned long long bb0 = pack2(bj[0], bj[1]);
            const unsigned long long bb1 = pack2(bj[2], bj[3]);
            const unsigned long long bb2 = pack2(bj[4], bj[5]);
            const unsigned long long bb3 = pack2(bj[6], bj[7]);
            const float ar[8] = {a0.x, a0.y, a0.z, a0.w, a1.x, a1.y, a1.z, a1.w};
#pragma unroll
            for (int i = 0; i < 8; ++i) {
                const unsigned long long aa = pack2(ar[i], ar[i]);
                acc[i][0] = fma2(aa, bb0, acc[i][0]);
                acc[i][1] = fma2(aa, bb1, acc[i][1]);
                acc[i][2] = fma2(aa, bb2, acc[i][2]);
                acc[i][3] = fma2(aa, bb3, acc[i][3]);
            }
        }
        __syncthreads();
    }

    // ---- epilogue ----
    float bv[8];
#pragma unroll
    for (int j = 0; j < 8; ++j)
        bv[j] = BIAS ? bias[bn * TN + tx + 16 * j] : 0.0f;

#pragma unroll
    for (int i = 0; i < 8; ++i) {
        const int row = bm * TM + ty * 8 + i;
        float* crow = C + (size_t)row * N + bn * TN;
#pragma unroll
        for (int p = 0; p < 4; ++p) {
            float lo, hi;
            unpack2(acc[i][p], lo, hi);
            crow[tx + 16 * (2 * p)] = lo + bv[2 * p];
            crow[tx + 16 * (2 * p + 1)] = hi + bv[2 * p + 1];
        }
    }
}

// In-place row softmax, row length TV=2048, one block (256 thr) per row.
__global__ void softmax_kernel(float* __restrict__ S) {
    const int tid = threadIdx.x;
    float* p = S + (size_t)blockIdx.x * TV;

    float v[8];
    {
        const float4 x0 = *(const float4*)(p + tid * 8);
        const float4 x1 = *(const float4*)(p + tid * 8 + 4);
        v[0] = x0.x; v[1] = x0.y; v[2] = x0.z; v[3] = x0.w;
        v[4] = x1.x; v[5] = x1.y; v[6] = x1.z; v[7] = x1.w;
    }

    __shared__ float red[16];
    const int lane = tid & 31;
    const int wid = tid >> 5;

    // max
    float m = v[0];
#pragma unroll
    for (int i = 1; i < 8; ++i) m = fmaxf(m, v[i]);
#pragma unroll
    for (int o = 16; o > 0; o >>= 1) m = fmaxf(m, __shfl_xor_sync(0xffffffffu, m, o));
    if (lane == 0) red[wid] = m;
    __syncthreads();
    if (tid == 0) {
        float mm = red[0];
#pragma unroll
        for (int i = 1; i < 8; ++i) mm = fmaxf(mm, red[i]);
        red[0] = mm;
    }
    __syncthreads();
    m = red[0];

    // exp + sum
    float s = 0.0f;
#pragma unroll
    for (int i = 0; i < 8; ++i) {
        v[i] = __expf(v[i] - m);
        s += v[i];
    }
#pragma unroll
    for (int o = 16; o > 0; o >>= 1) s += __shfl_xor_sync(0xffffffffu, s, o);
    if (lane == 0) red[8 + wid] = s;
    __syncthreads();
    if (tid == 0) {
        float ss = red[8];
#pragma unroll
        for (int i = 1; i < 8; ++i) ss += red[8 + i];
        red[8] = ss;
    }
    __syncthreads();
    const float inv = 1.0f / red[8];

    float4 y0, y1;
    y0.x = v[0] * inv; y0.y = v[1] * inv; y0.z = v[2] * inv; y0.w = v[3] * inv;
    y1.x = v[4] * inv; y1.y = v[5] * inv; y1.z = v[6] * inv; y1.w = v[7] * inv;
    *(float4*)(p + tid * 8) = y0;
    *(float4*)(p + tid * 8 + 4) = y1;
}

extern "C" void kernel_launch(void* const* d_in, const int* in_sizes, int n_in,
                              void* d_out, int out_size) {
    (void)in_sizes; (void)n_in; (void)out_size;
    const float* query  = (const float*)d_in[0];   // [B, TQ, UNITS]
    const float* values = (const float*)d_in[1];   // [B, TV, D]
    const float* Wk     = (const float*)d_in[2];   // [D, UNITS]
    const float* Wb     = (const float*)d_in[3];   // [UNITS]

    float* context = (float*)d_out;                                   // [B, TQ, D]
    float* align   = (float*)d_out + (size_t)B_DIM * TQ * D_DIM;      // [B, TQ, TV]

    float* keys = nullptr;
    cudaGetSymbolAddress((void**)&keys, g_keys);

    // 1) keys = values @ W + b   (flatten batch: [B*TV, D] @ [D, UNITS])
    {
        dim3 grid(UNITS / TN, (B_DIM * TV) / TM, 1);
        gemm_f32x2_kernel<false, true><<<grid, 256>>>(
            values, Wk, Wb, keys, B_DIM * TV, UNITS, D_DIM, 0, 0, 0);
    }

    // 2) score[b] = query[b] @ keys[b]^T  -> alignment buffer
    {
        dim3 grid(TV / TN, TQ / TM, B_DIM);
        gemm_f32x2_kernel<true, false><<<grid, 256>>>(
            query, keys, nullptr, align, TQ, TV, UNITS,
            (size_t)TQ * UNITS, (size_t)TV * UNITS, (size_t)TQ * TV);
    }

    // 3) softmax in place over last dim
    softmax_kernel<<<B_DIM * TQ, 256>>>(align);

    // 4) context[b] = align[b] @ values[b]
    {
        dim3 grid(D_DIM / TN, TQ / TM, B_DIM);
        gemm_f32x2_kernel<false, false><<<grid, 256>>>(
            align, values, nullptr, context, TQ, D_DIM, TV,
            (size_t)TQ * TV, (size_t)TV * D_DIM, (size_t)TQ * D_DIM);
    }
}

// round 4
// speedup vs baseline: 2.3269x; 2.3269x over previous
#include <cuda_runtime.h>
#include <cuda_bf16.h>
#include <cstdint>
#include <cstddef>

// ---------------------------------------------------------------------------
// LuongAttention via bf16 hi/lo 3-pass mma.sync (HMMA, baseline PTX — works on
// compute_103 targets where tcgen05 is unavailable).
//   keys    = values @ W + b      [B, TV, U]   (split epilogue -> bf16 hi/lo)
//   score   = query @ keys^T      [B, TQ, TV]  (fp32 out, into align buffer)
//   align   = softmax(score)                   (fp32 in place + hi/lo split)
//   context = align @ values      [B, TQ, D]   (fp32 out)
// ---------------------------------------------------------------------------

#define B_DIM 16
#define TQ 2048
#define TV 2048
#define D_DIM 1024
#define UNITS 1024

typedef __nv_bfloat16 bf16;

#define NQ ((size_t)B_DIM * TQ * UNITS)
#define NV ((size_t)B_DIM * TV * D_DIM)
#define NK ((size_t)B_DIM * TV * UNITS)
#define NS ((size_t)B_DIM * TQ * TV)

__device__ bf16 g_Qhi[NQ], g_Qlo[NQ];
__device__ bf16 g_Vhi[NV], g_Vlo[NV];
__device__ bf16 g_VThi[NV], g_VTlo[NV];     // values^T per batch: [D, TV]
__device__ bf16 g_Khi[NK], g_Klo[NK];
__device__ bf16 g_WThi[D_DIM * UNITS], g_WTlo[D_DIM * UNITS];   // W^T: [U, D]
__device__ bf16 g_Ahi[NS], g_Alo[NS];

// ---------------------------------------------------------------------------
__device__ __forceinline__ uint32_t smem_u32(const void* p) {
    uint32_t a;
    asm("{ .reg .u64 t; cvta.to.shared.u64 t, %1; cvt.u32.u64 %0, t; }"
        : "=r"(a) : "l"(p));
    return a;
}

#define CP_ASYNC16(dst, src) \
    asm volatile("cp.async.cg.shared.global [%0], [%1], 16;" \
                 :: "r"(dst), "l"(src) : "memory")
#define CP_COMMIT() asm volatile("cp.async.commit_group;" ::: "memory")
#define CP_WAIT0()  asm volatile("cp.async.wait_group 0;" ::: "memory")

__device__ __forceinline__ void ldsm4(uint32_t& r0, uint32_t& r1,
                                      uint32_t& r2, uint32_t& r3, uint32_t addr) {
    asm volatile("ldmatrix.sync.aligned.m8n8.x4.shared.b16 {%0,%1,%2,%3}, [%4];"
                 : "=r"(r0), "=r"(r1), "=r"(r2), "=r"(r3) : "r"(addr));
}

__device__ __forceinline__ void mma16816(float* d, const uint32_t* a, const uint32_t* b) {
    asm volatile("mma.sync.aligned.m16n8k16.row.col.f32.bf16.bf16.f32 "
                 "{%0,%1,%2,%3},{%4,%5,%6,%7},{%8,%9},{%0,%1,%2,%3};"
                 : "+f"(d[0]), "+f"(d[1]), "+f"(d[2]), "+f"(d[3])
                 : "r"(a[0]), "r"(a[1]), "r"(a[2]), "r"(a[3]), "r"(b[0]), "r"(b[1]));
}

// ---------------------------------------------------------------------------
// SMEM layout: padded rows (32 bf16 data + 8 pad = 80 B) => conflict-free ldmatrix.
// Per stage: Ahi | Alo | Bhi | Blo, each 128 rows x 80 B = 10240 B. Stage = 40960 B.
// ---------------------------------------------------------------------------
#define ROWB 80u
#define OP_SZ 10240u
#define ST_SZ 40960u
#define SM_TOTAL (2u * ST_SZ)

// C[M,N] = (Ahi+Alo)[M,K] @ (Bhi+Blo)[N,K]^T  (3-pass), batched via blockIdx.z.
// EPI=0: fp32 C.  EPI=1: +bias, split to Chi/Clo bf16.
template <int EPI>
__global__ void __launch_bounds__(256, 2)
hmma_gemm_kernel(const bf16* __restrict__ Ahi_, const bf16* __restrict__ Alo_,
                 const bf16* __restrict__ Bhi_, const bf16* __restrict__ Blo_,
                 const float* __restrict__ bias,
                 float* __restrict__ Cf_, bf16* __restrict__ Chi_, bf16* __restrict__ Clo_,
                 int M, int N, int K,
                 size_t sA, size_t sB, size_t sC) {
    extern __shared__ char smc[];
    const uint32_t sb = smem_u32(smc);
    const int tid = threadIdx.x, lane = tid & 31, wid = tid >> 5;
    const int wm = wid >> 2, wn = wid & 3;        // 2 x 4 warps, warp tile 64x32
    const int bn = blockIdx.x, bm = blockIdx.y, bz = blockIdx.z;

    const bf16* Ah = Ahi_ + (size_t)bz * sA;
    const bf16* Al = Alo_ + (size_t)bz * sA;
    const bf16* Bh = Bhi_ + (size_t)bz * sB;
    const bf16* Bl = Blo_ + (size_t)bz * sB;

    float acc[4][4][4];
#pragma unroll
    for (int i = 0; i < 4; ++i)
#pragma unroll
        for (int j = 0; j < 4; ++j)
#pragma unroll
            for (int p = 0; p < 4; ++p) acc[i][j][p] = 0.0f;

    // per-thread load coords: 2 x (row, 16B col) per operand
    const int lr0 = tid >> 2, lc = (tid & 3) * 16;        // row 0..63, bytecol
    const int le = (tid & 3) * 8;                          // element col
    const uint32_t so0 = (uint32_t)lr0 * ROWB + lc;
    const uint32_t so1 = (uint32_t)(lr0 + 64) * ROWB + lc;

    // ldmatrix base offsets (within an operand region)
    const uint32_t a_off = (uint32_t)(wm * 64 + (lane & 15)) * ROWB + ((lane >> 4) * 16);
    const uint32_t b_off = (uint32_t)(wn * 32 + ((lane >> 4) << 3) + (lane & 7)) * ROWB +
                           (((lane >> 3) & 1) * 16);

    const int nk = K / 32;

    // prologue: stage 0 loads
    {
        const size_t ga0 = (size_t)(bm * 128 + lr0) * K + le;
        const size_t ga1 = (size_t)(bm * 128 + lr0 + 64) * K + le;
        const size_t gb0 = (size_t)(bn * 128 + lr0) * K + le;
        const size_t gb1 = (size_t)(bn * 128 + lr0 + 64) * K + le;
        CP_ASYNC16(sb + so0, Ah + ga0);            CP_ASYNC16(sb + so1, Ah + ga1);
        CP_ASYNC16(sb + OP_SZ + so0, Al + ga0);    CP_ASYNC16(sb + OP_SZ + so1, Al + ga1);
        CP_ASYNC16(sb + 2*OP_SZ + so0, Bh + gb0);  CP_ASYNC16(sb + 2*OP_SZ + so1, Bh + gb1);
        CP_ASYNC16(sb + 3*OP_SZ + so0, Bl + gb0);  CP_ASYNC16(sb + 3*OP_SZ + so1, Bl + gb1);
        CP_COMMIT();
    }

    for (int kt = 0; kt < nk; ++kt) {
        CP_WAIT0();
        __syncthreads();

        if (kt + 1 < nk) {
            const uint32_t s0 = sb + ((kt + 1) & 1) * ST_SZ;
            const size_t kc = (size_t)(kt + 1) * 32;
            const size_t ga0 = (size_t)(bm * 128 + lr0) * K + kc + le;
            const size_t ga1 = (size_t)(bm * 128 + lr0 + 64) * K + kc + le;
            const size_t gb0 = (size_t)(bn * 128 + lr0) * K + kc + le;
            const size_t gb1 = (size_t)(bn * 128 + lr0 + 64) * K + kc + le;
            CP_ASYNC16(s0 + so0, Ah + ga0);            CP_ASYNC16(s0 + so1, Ah + ga1);
            CP_ASYNC16(s0 + OP_SZ + so0, Al + ga0);    CP_ASYNC16(s0 + OP_SZ + so1, Al + ga1);
            CP_ASYNC16(s0 + 2*OP_SZ + so0, Bh + gb0);  CP_ASYNC16(s0 + 2*OP_SZ + so1, Bh + gb1);
            CP_ASYNC16(s0 + 3*OP_SZ + so0, Bl + gb0);  CP_ASYNC16(s0 + 3*OP_SZ + so1, Bl + gb1);
            CP_COMMIT();
        }

        const uint32_t s0 = sb + (kt & 1) * ST_SZ;
#pragma unroll
        for (int ks = 0; ks < 2; ++ks) {
            const uint32_t kofs = ks * 32;
            uint32_t ahf[4][4], bhf[2][4];
#pragma unroll
            for (int mi = 0; mi < 4; ++mi)
                ldsm4(ahf[mi][0], ahf[mi][1], ahf[mi][2], ahf[mi][3],
                      s0 + a_off + mi * (16 * ROWB) + kofs);
#pragma unroll
            for (int np = 0; np < 2; ++np)
                ldsm4(bhf[np][0], bhf[np][1], bhf[np][2], bhf[np][3],
                      s0 + 2*OP_SZ + b_off + np * (16 * ROWB) + kofs);
            // pass 1: hi * hi
#pragma unroll
            for (int mi = 0; mi < 4; ++mi)
#pragma unroll
                for (int ni = 0; ni < 4; ++ni)
                    mma16816(acc[mi][ni], ahf[mi], &bhf[ni >> 1][(ni & 1) * 2]);
            // pass 2: hi * lo
            {
                uint32_t blf[2][4];
#pragma unroll
                for (int np = 0; np < 2; ++np)
                    ldsm4(blf[np][0], blf[np][1], blf[np][2], blf[np][3],
                          s0 + 3*OP_SZ + b_off + np * (16 * ROWB) + kofs);
#pragma unroll
                for (int mi = 0; mi < 4; ++mi)
#pragma unroll
                    for (int ni = 0; ni < 4; ++ni)
                        mma16816(acc[mi][ni], ahf[mi], &blf[ni >> 1][(ni & 1) * 2]);
            }
            // pass 3: lo * hi
            {
                uint32_t alf[4][4];
#pragma unroll
                for (int mi = 0; mi < 4; ++mi)
                    ldsm4(alf[mi][0], alf[mi][1], alf[mi][2], alf[mi][3],
                          s0 + OP_SZ + a_off + mi * (16 * ROWB) + kofs);
#pragma unroll
                for (int mi = 0; mi < 4; ++mi)
#pragma unroll
                    for (int ni = 0; ni < 4; ++ni)
                        mma16816(acc[mi][ni], alf[mi], &bhf[ni >> 1][(ni & 1) * 2]);
            }
        }
        __syncthreads();
    }

    // ---- epilogue ----
    const int row0 = bm * 128 + wm * 64 + (lane >> 2);
    const int col0 = bn * 128 + wn * 32 + (lane & 3) * 2;
#pragma unroll
    for (int mi = 0; mi < 4; ++mi)
#pragma unroll
        for (int h = 0; h < 2; ++h) {
            const int row = row0 + mi * 16 + h * 8;
#pragma unroll
            for (int ni = 0; ni < 4; ++ni) {
                const int col = col0 + ni * 8;
                const float v0 = acc[mi][ni][2 * h];
                const float v1 = acc[mi][ni][2 * h + 1];
                if (EPI == 0) {
                    float2 o; o.x = v0; o.y = v1;
                    *(float2*)(Cf_ + (size_t)bz * sC + (size_t)row * N + col) = o;
                } else {
                    const float f0 = v0 + bias[col];
                    const float f1 = v1 + bias[col + 1];
                    const bf16 h0 = __float2bfloat16_rn(f0);
                    const bf16 h1 = __float2bfloat16_rn(f1);
                    __nv_bfloat162 hh, ll;
                    hh.x = h0; hh.y = h1;
                    ll.x = __float2bfloat16_rn(f0 - __bfloat162float(h0));
                    ll.y = __float2bfloat16_rn(f1 - __bfloat162float(h1));
                    const size_t o = (size_t)row * N + col;
                    *(__nv_bfloat162*)(Chi_ + o) = hh;
                    *(__nv_bfloat162*)(Clo_ + o) = ll;
                }
            }
        }
}

// ---------------------------------------------------------------------------
__global__ void split_kernel(const float* __restrict__ x,
                             bf16* __restrict__ hi, bf16* __restrict__ lo, size_t n4) {
    const size_t i = (size_t)blockIdx.x * blockDim.x + threadIdx.x;
    if (i >= n4) return;
    const float4 v = ((const float4*)x)[i];
    const float f[4] = {v.x, v.y, v.z, v.w};
    __nv_bfloat162 h2[2], l2[2];
#pragma unroll
    for (int j = 0; j < 2; ++j) {
        const bf16 h0 = __float2bfloat16_rn(f[2 * j]);
        const bf16 h1 = __float2bfloat16_rn(f[2 * j + 1]);
        h2[j].x = h0; h2[j].y = h1;
        l2[j].x = __float2bfloat16_rn(f[2 * j] - __bfloat162float(h0));
        l2[j].y = __float2bfloat16_rn(f[2 * j + 1] - __bfloat162float(h1));
    }
    ((__nv_bfloat162*)hi)[2 * i] = h2[0];
    ((__nv_bfloat162*)hi)[2 * i + 1] = h2[1];
    ((__nv_bfloat162*)lo)[2 * i] = l2[0];
    ((__nv_bfloat162*)lo)[2 * i + 1] = l2[1];
}

__global__ void transpose_split_kernel(const float* __restrict__ in,
                                       bf16* __restrict__ shi, bf16* __restrict__ slo,
                                       bf16* __restrict__ thi, bf16* __restrict__ tlo,
                                       int rows, int cols) {
    __shared__ float tile[32][33];
    const int tx = threadIdx.x, ty = threadIdx.y;
    const int bx = blockIdx.x, by = blockIdx.y, bz = blockIdx.z;
    const size_t base = (size_t)bz * rows * cols;
    const int x = bx * 32 + tx;

#pragma unroll
    for (int j = 0; j < 4; ++j) {
        const int r = by * 32 + ty + j * 8;
        const float v = in[base + (size_t)r * cols + x];
        tile[ty + j * 8][tx] = v;
        if (shi) {
            const bf16 h = __float2bfloat16_rn(v);
            shi[base + (size_t)r * cols + x] = h;
            slo[base + (size_t)r * cols + x] =
                __float2bfloat16_rn(v - __bfloat162float(h));
        }
    }
    __syncthreads();
#pragma unroll
    for (int j = 0; j < 4; ++j) {
        const int r = ty + j * 8;
        const float v = tile[tx][r];
        const int orow = bx * 32 + r;
        const int ocol = by * 32 + tx;
        const bf16 h = __float2bfloat16_rn(v);
        thi[base + (size_t)orow * rows + ocol] = h;
        tlo[base + (size_t)orow * rows + ocol] =
            __float2bfloat16_rn(v - __bfloat162float(h));
    }
}

__global__ void softmax_split_kernel(float* __restrict__ S,
                                     bf16* __restrict__ Ahi, bf16* __restrict__ Alo) {
    const int tid = threadIdx.x;
    const size_t rowoff = (size_t)blockIdx.x * TV;
    float* p = S + rowoff;

    float v[8];
    {
        const float4 x0 = *(const float4*)(p + tid * 8);
        const float4 x1 = *(const float4*)(p + tid * 8 + 4);
        v[0] = x0.x; v[1] = x0.y; v[2] = x0.z; v[3] = x0.w;
        v[4] = x1.x; v[5] = x1.y; v[6] = x1.z; v[7] = x1.w;
    }

    __shared__ float red[16];
    const int lane = tid & 31, wid = tid >> 5;

    float m = v[0];
#pragma unroll
    for (int i = 1; i < 8; ++i) m = fmaxf(m, v[i]);
#pragma unroll
    for (int o = 16; o > 0; o >>= 1) m = fmaxf(m, __shfl_xor_sync(0xffffffffu, m, o));
    if (lane == 0) red[wid] = m;
    __syncthreads();
    if (tid == 0) {
        float mm = red[0];
#pragma unroll
        for (int i = 1; i < 8; ++i) mm = fmaxf(mm, red[i]);
        red[0] = mm;
    }
    __syncthreads();
    m = red[0];

    float s = 0.0f;
#pragma unroll
    for (int i = 0; i < 8; ++i) { v[i] = __expf(v[i] - m); s += v[i]; }
#pragma unroll
    for (int o = 16; o > 0; o >>= 1) s += __shfl_xor_sync(0xffffffffu, s, o);
    if (lane == 0) red[8 + wid] = s;
    __syncthreads();
    if (tid == 0) {
        float ss = red[8];
#pragma unroll
        for (int i = 1; i < 8; ++i) ss += red[8 + i];
        red[8] = ss;
    }
    __syncthreads();
    const float inv = 1.0f / red[8];

    float y[8];
#pragma unroll
    for (int i = 0; i < 8; ++i) y[i] = v[i] * inv;

    float4 o0, o1;
    o0.x = y[0]; o0.y = y[1]; o0.z = y[2]; o0.w = y[3];
    o1.x = y[4]; o1.y = y[5]; o1.z = y[6]; o1.w = y[7];
    *(float4*)(p + tid * 8) = o0;
    *(float4*)(p + tid * 8 + 4) = o1;

#pragma unroll
    for (int j = 0; j < 4; ++j) {
        const bf16 h0 = __float2bfloat16_rn(y[2 * j]);
        const bf16 h1 = __float2bfloat16_rn(y[2 * j + 1]);
        __nv_bfloat162 h2; h2.x = h0; h2.y = h1;
        __nv_bfloat162 l2;
        l2.x = __float2bfloat16_rn(y[2 * j] - __bfloat162float(h0));
        l2.y = __float2bfloat16_rn(y[2 * j + 1] - __bfloat162float(h1));
        *(__nv_bfloat162*)(Ahi + rowoff + tid * 8 + 2 * j) = h2;
        *(__nv_bfloat162*)(Alo + rowoff + tid * 8 + 2 * j) = l2;
    }
}

// ---------------------------------------------------------------------------
extern "C" void kernel_launch(void* const* d_in, const int* in_sizes, int n_in,
                              void* d_out, int out_size) {
    (void)in_sizes; (void)n_in; (void)out_size;
    const float* query  = (const float*)d_in[0];   // [B, TQ, UNITS]
    const float* values = (const float*)d_in[1];   // [B, TV, D]
    const float* Wk     = (const float*)d_in[2];   // [D, UNITS]
    const float* Wb     = (const float*)d_in[3];   // [UNITS]

    float* context = (float*)d_out;                               // [B, TQ, D]
    float* align   = (float*)d_out + (size_t)B_DIM * TQ * D_DIM;  // [B, TQ, TV]

    bf16 *Qhi, *Qlo, *Vhi, *Vlo, *VThi, *VTlo, *Khi, *Klo, *WThi, *WTlo, *Ahi, *Alo;
    cudaGetSymbolAddress((void**)&Qhi, g_Qhi);   cudaGetSymbolAddress((void**)&Qlo, g_Qlo);
    cudaGetSymbolAddress((void**)&Vhi, g_Vhi);   cudaGetSymbolAddress((void**)&Vlo, g_Vlo);
    cudaGetSymbolAddress((void**)&VThi, g_VThi); cudaGetSymbolAddress((void**)&VTlo, g_VTlo);
    cudaGetSymbolAddress((void**)&Khi, g_Khi);   cudaGetSymbolAddress((void**)&Klo, g_Klo);
    cudaGetSymbolAddress((void**)&WThi, g_WThi); cudaGetSymbolAddress((void**)&WTlo, g_WTlo);
    cudaGetSymbolAddress((void**)&Ahi, g_Ahi);   cudaGetSymbolAddress((void**)&Alo, g_Alo);

    cudaFuncSetAttribute(hmma_gemm_kernel<0>,
                         cudaFuncAttributeMaxDynamicSharedMemorySize, SM_TOTAL);
    cudaFuncSetAttribute(hmma_gemm_kernel<1>,
                         cudaFuncAttributeMaxDynamicSharedMemorySize, SM_TOTAL);

    // 1) splits
    split_kernel<<<(unsigned)(NQ / 4 / 256), 256>>>(query, Qhi, Qlo, NQ / 4);
    {
        dim3 grid(D_DIM / 32, TV / 32, B_DIM);
        transpose_split_kernel<<<grid, dim3(32, 8)>>>(values, Vhi, Vlo, VThi, VTlo,
                                                      TV, D_DIM);
    }
    {
        dim3 grid(UNITS / 32, D_DIM / 32, 1);
        transpose_split_kernel<<<grid, dim3(32, 8)>>>(Wk, nullptr, nullptr, WThi, WTlo,
                                                      D_DIM, UNITS);
    }

    // 2) keys = values @ W + b  (M=B*TV, N=UNITS, K=D), split epilogue
    {
        dim3 grid(UNITS / 128, (B_DIM * TV) / 128, 1);
        hmma_gemm_kernel<1><<<grid, 256, SM_TOTAL>>>(
            Vhi, Vlo, WThi, WTlo, Wb, nullptr, Khi, Klo,
            B_DIM * TV, UNITS, D_DIM, 0, 0, 0);
    }

    // 3) score = Q @ K^T per batch -> align buffer (fp32)
    {
        dim3 grid(TV / 128, TQ / 128, B_DIM);
        hmma_gemm_kernel<0><<<grid, 256, SM_TOTAL>>>(
            Qhi, Qlo, Khi, Klo, nullptr, align, nullptr, nullptr,
            TQ, TV, UNITS,
            (size_t)TQ * UNITS, (size_t)TV * UNITS, (size_t)TQ * TV);
    }

    // 4) softmax in place + split emit
    softmax_split_kernel<<<B_DIM * TQ, 256>>>(align, Ahi, Alo);

    // 5) context = align @ values per batch (B operand = values^T [D, TV])
    {
        dim3 grid(D_DIM / 128, TQ / 128, B_DIM);
        hmma_gemm_kernel<0><<<grid, 256, SM_TOTAL>>>(
            Ahi, Alo, VThi, VTlo, nullptr, context, nullptr, nullptr,
            TQ, D_DIM, TV,
            (size_t)TQ * TV, (size_t)D_DIM * TV, (size_t)TQ * D_DIM);
    }
}